// round 3
// baseline (speedup 1.0000x reference)
#include <cuda_runtime.h>

// Decoder_8014408974552 — fused GRU decoder recurrence.
// B=32768, T=30, H=384.
//
// Key restructuring: the entire input path
//   x = (state@Ws.T+bs) + (plan_t@Wp.T+bp)*gate ; gi = x@W_ih.T + b_ih
// folds into gi[j] = C2[j] + state·M2[j,:] + gate*(C1[j] + plan_t·M1[j,:])
// with M1=W_ih@Wp [1152,3], M2=W_ih@Ws [1152,3], C1=W_ih@bp, C2=W_ih@bs+b_ih
// (exact reordering). Remaining per-step work: gh = hidden@W_hh.T (dominant),
// GRU pointwise, decode MLP 384->64->3, state += dec.
//
// The recurrence is independent per batch row -> each CTA owns 32 rows,
// keeps hidden (double-buffered) + state in SMEM, loops all 30 steps.
// No grid sync. fp32 throughout (rel_err target ~1e-5).

#define NB       32768
#define NT       30
#define NH       384
#define ROWS     32
#define NTHREADS 256
#define HPAD     388   // 384 + 4: float4-aligned, conflict-free LDS.128
#define H64PAD   65    // 64 + 1: conflict-free scalar access

#define SMEM_FLOATS (2*ROWS*HPAD + ROWS*H64PAD + ROWS*3 + ROWS*3 + ROWS)
#define SMEM_BYTES  (SMEM_FLOATS * 4)

// Folded input-path coefficients (written by precompute_kernel every launch).
__device__ float g_M1[1152 * 3];
__device__ float g_M2[1152 * 3];
__device__ float g_C1[1152];
__device__ float g_C2[1152];

__global__ void precompute_kernel(const float* __restrict__ Wp,
                                  const float* __restrict__ bp,
                                  const float* __restrict__ Ws,
                                  const float* __restrict__ bs,
                                  const float* __restrict__ Wih,
                                  const float* __restrict__ bih)
{
    int j = blockIdx.x * blockDim.x + threadIdx.x;
    if (j >= 1152) return;
    const float* wr = Wih + j * 128;
    float m10 = 0.f, m11 = 0.f, m12 = 0.f;
    float m20 = 0.f, m21 = 0.f, m22 = 0.f;
    float c1 = 0.f, c2 = 0.f;
#pragma unroll 4
    for (int i = 0; i < 128; ++i) {
        float w = wr[i];
        m10 = fmaf(w, Wp[i * 3 + 0], m10);
        m11 = fmaf(w, Wp[i * 3 + 1], m11);
        m12 = fmaf(w, Wp[i * 3 + 2], m12);
        m20 = fmaf(w, Ws[i * 3 + 0], m20);
        m21 = fmaf(w, Ws[i * 3 + 1], m21);
        m22 = fmaf(w, Ws[i * 3 + 2], m22);
        c1  = fmaf(w, bp[i], c1);
        c2  = fmaf(w, bs[i], c2);
    }
    g_M1[j * 3 + 0] = m10; g_M1[j * 3 + 1] = m11; g_M1[j * 3 + 2] = m12;
    g_M2[j * 3 + 0] = m20; g_M2[j * 3 + 1] = m21; g_M2[j * 3 + 2] = m22;
    g_C1[j] = c1;
    g_C2[j] = c2 + bih[j];
}

__device__ __forceinline__ float sigf(float x)
{
    return 1.0f / (1.0f + __expf(-x));
}
__device__ __forceinline__ float tanh_f(float x)
{
    // 1 - 2/(e^{2x}+1): abs error ~1e-7, robust at extremes.
    return 1.0f - 2.0f / (__expf(2.0f * x) + 1.0f);
}

__global__ void __launch_bounds__(NTHREADS, 2)
decoder_kernel(const float* __restrict__ init_hidden,
               const float* __restrict__ plan,
               const float* __restrict__ gate,
               const float* __restrict__ init_state,
               const float* __restrict__ Whh,
               const float* __restrict__ bhh,
               const float* __restrict__ Wd1,
               const float* __restrict__ bd1,
               const float* __restrict__ Wd2,
               const float* __restrict__ bd2,
               float* __restrict__ out)
{
    extern __shared__ float smem[];
    float* sh_h     = smem;                       // [2][ROWS][HPAD]
    float* sh_h64   = smem + 2 * ROWS * HPAD;     // [ROWS][H64PAD]
    float* sh_state = sh_h64 + ROWS * H64PAD;     // [ROWS][3]
    float* sh_plan  = sh_state + ROWS * 3;        // [ROWS][3]
    float* sh_gate  = sh_plan + ROWS * 3;         // [ROWS]

    const int tid  = threadIdx.x;
    const int warp = tid >> 5;
    const int lane = tid & 31;
    const int row0 = blockIdx.x * ROWS;

    // ---- init: hidden, state, plan[t=0], gate ----
    for (int i = tid; i < ROWS * NH; i += NTHREADS) {
        int r = i / NH, c = i - r * NH;
        sh_h[r * HPAD + c] = init_hidden[(size_t)(row0 + r) * NH + c];
    }
    for (int i = tid; i < ROWS * 3; i += NTHREADS) {
        sh_state[i] = init_state[(size_t)row0 * 3 + i];
        int r = i / 3, c = i - r * 3;
        sh_plan[i] = plan[((size_t)(row0 + r) * NT) * 3 + c];
    }
    if (tid < ROWS) sh_gate[tid] = gate[row0 + tid];
    __syncthreads();

    const int b = lane;  // each warp covers all 32 rows; warps split units

    for (int t = 0; t < NT; ++t) {
        float* hcur = sh_h + (t & 1) * (ROWS * HPAD);
        float* hnxt = sh_h + ((t & 1) ^ 1) * (ROWS * HPAD);

        // per-row scalars for folded gi
        const float st0 = sh_state[b * 3 + 0];
        const float st1 = sh_state[b * 3 + 1];
        const float st2 = sh_state[b * 3 + 2];
        const float g   = sh_gate[b];
        const float gp0 = g * sh_plan[b * 3 + 0];
        const float gp1 = g * sh_plan[b * 3 + 1];
        const float gp2 = g * sh_plan[b * 3 + 2];
        const float4* hrow = (const float4*)(hcur + b * HPAD);

        // ======== Phase 1: GRU. warp w -> units [48w, 48w+48) ========
        for (int jj = warp * 48; jj < warp * 48 + 48; jj += 4) {
            float accr[4], accz[4], accn[4];
            const float4* wps[4];
#pragma unroll
            for (int u = 0; u < 4; ++u) {
                wps[u]  = (const float4*)(Whh + (size_t)(jj + u) * NH);
                accr[u] = __ldg(bhh + jj + u);
                accz[u] = __ldg(bhh + 384 + jj + u);
                accn[u] = __ldg(bhh + 768 + jj + u);
            }
            // W_hh rows for z/n gates sit at fixed float4 offsets:
            // +384*384/4 = 36864, +768*384/4 = 73728 (fits LDG imm offset).
#pragma unroll 2
            for (int k4 = 0; k4 < NH / 4; ++k4) {
                const float4 h = hrow[k4];
#pragma unroll
                for (int u = 0; u < 4; ++u) {
                    const float4 wr = __ldg(wps[u] + k4);
                    const float4 wz = __ldg(wps[u] + k4 + 36864);
                    const float4 wn = __ldg(wps[u] + k4 + 73728);
                    accr[u] = fmaf(h.w, wr.w, fmaf(h.z, wr.z,
                              fmaf(h.y, wr.y, fmaf(h.x, wr.x, accr[u]))));
                    accz[u] = fmaf(h.w, wz.w, fmaf(h.z, wz.z,
                              fmaf(h.y, wz.y, fmaf(h.x, wz.x, accz[u]))));
                    accn[u] = fmaf(h.w, wn.w, fmaf(h.z, wn.z,
                              fmaf(h.y, wn.y, fmaf(h.x, wn.x, accn[u]))));
                }
            }
#pragma unroll
            for (int u = 0; u < 4; ++u) {
                const int j  = jj + u;
                const int jz = j + 384;
                const int jn = j + 768;
                float gir = g_C2[j] + g * g_C1[j]
                          + st0 * g_M2[j * 3 + 0] + st1 * g_M2[j * 3 + 1]
                          + st2 * g_M2[j * 3 + 2]
                          + gp0 * g_M1[j * 3 + 0] + gp1 * g_M1[j * 3 + 1]
                          + gp2 * g_M1[j * 3 + 2];
                float giz = g_C2[jz] + g * g_C1[jz]
                          + st0 * g_M2[jz * 3 + 0] + st1 * g_M2[jz * 3 + 1]
                          + st2 * g_M2[jz * 3 + 2]
                          + gp0 * g_M1[jz * 3 + 0] + gp1 * g_M1[jz * 3 + 1]
                          + gp2 * g_M1[jz * 3 + 2];
                float gin = g_C2[jn] + g * g_C1[jn]
                          + st0 * g_M2[jn * 3 + 0] + st1 * g_M2[jn * 3 + 1]
                          + st2 * g_M2[jn * 3 + 2]
                          + gp0 * g_M1[jn * 3 + 0] + gp1 * g_M1[jn * 3 + 1]
                          + gp2 * g_M1[jn * 3 + 2];

                float r = sigf(gir + accr[u]);
                float z = sigf(giz + accz[u]);
                float n = tanh_f(gin + r * accn[u]);
                float hold = hcur[b * HPAD + j];
                hnxt[b * HPAD + j] = n + z * (hold - n);
            }
        }
        __syncthreads();

        // ======== Phase 2: decode layer 1 (384 -> 64) + ELU ========
        {
            const float4* hrow2 = (const float4*)(hnxt + b * HPAD);
            const int u0 = warp * 8;  // warp w -> units [8w, 8w+8)
            float acc[8];
            const float4* wd[8];
#pragma unroll
            for (int u = 0; u < 8; ++u) {
                acc[u] = __ldg(bd1 + u0 + u);
                wd[u]  = (const float4*)(Wd1 + (size_t)(u0 + u) * NH);
            }
#pragma unroll 2
            for (int k4 = 0; k4 < NH / 4; ++k4) {
                const float4 h = hrow2[k4];
#pragma unroll
                for (int u = 0; u < 8; ++u) {
                    const float4 w = __ldg(wd[u] + k4);
                    acc[u] = fmaf(h.w, w.w, fmaf(h.z, w.z,
                             fmaf(h.y, w.y, fmaf(h.x, w.x, acc[u]))));
                }
            }
#pragma unroll
            for (int u = 0; u < 8; ++u) {
                float v = acc[u];
                sh_h64[b * H64PAD + u0 + u] =
                    (v > 0.0f) ? v : (__expf(v) - 1.0f);  // ELU(alpha=1)
            }
        }
        __syncthreads();

        // ======== Phase 3: decode layer 2 (64 -> 3), state update, output ====
        if (tid < ROWS * 3) {
            const int br = tid / 3, v = tid - br * 3;
            const float* w2  = Wd2 + v * 64;
            const float* h64 = sh_h64 + br * H64PAD;
            float acc = __ldg(bd2 + v);
#pragma unroll
            for (int u = 0; u < 64; ++u) acc = fmaf(__ldg(w2 + u), h64[u], acc);
            float s = sh_state[tid] + acc;
            sh_state[tid] = s;
            out[((size_t)(row0 + br) * NT + t) * 3 + v] = s;
        } else if (tid >= 128 && tid < 128 + ROWS * 3) {
            // stage plan for next step in parallel with the state update
            if (t + 1 < NT) {
                const int i  = tid - 128;
                const int br = i / 3, c = i - br * 3;
                sh_plan[i] = plan[((size_t)(row0 + br) * NT + (t + 1)) * 3 + c];
            }
        }
        __syncthreads();
    }
}

extern "C" void kernel_launch(void* const* d_in, const int* in_sizes, int n_in,
                              void* d_out, int out_size)
{
    (void)in_sizes; (void)n_in; (void)out_size;
    const float* init_hidden = (const float*)d_in[0];
    const float* plan        = (const float*)d_in[1];
    const float* gate        = (const float*)d_in[2];
    const float* init_state  = (const float*)d_in[3];
    const float* Wp   = (const float*)d_in[4];
    const float* bp   = (const float*)d_in[5];
    const float* Ws   = (const float*)d_in[6];
    const float* bs   = (const float*)d_in[7];
    const float* W_ih = (const float*)d_in[8];
    const float* b_ih = (const float*)d_in[9];
    const float* W_hh = (const float*)d_in[10];
    const float* b_hh = (const float*)d_in[11];
    const float* Wd1  = (const float*)d_in[12];
    const float* bd1  = (const float*)d_in[13];
    const float* Wd2  = (const float*)d_in[14];
    const float* bd2  = (const float*)d_in[15];
    float* out = (float*)d_out;

    precompute_kernel<<<9, 128>>>(Wp, bp, Ws, bs, W_ih, b_ih);

    cudaFuncSetAttribute(decoder_kernel,
                         cudaFuncAttributeMaxDynamicSharedMemorySize,
                         SMEM_BYTES);
    decoder_kernel<<<NB / ROWS, NTHREADS, SMEM_BYTES>>>(
        init_hidden, plan, gate, init_state,
        W_hh, b_hh, Wd1, bd1, Wd2, bd2, out);
}

// round 4
// speedup vs baseline: 1.6327x; 1.6327x over previous
#include <cuda_runtime.h>

// Decoder_8014408974552 — fused GRU decoder recurrence. B=32768, T=30, H=384.
//
// R3 changes vs R2 (59.7ms, L1tex-bound at 85%):
//  * ROWS=64 per CTA, 2 rows per lane -> each weight LDG.128 feeds 64 rows
//    (halves LDG wavefronts).
//  * fma.rn.f32x2 paired over the K (reduction) dim: a float4 of h / w is
//    already two f32x2 pairs, zero packing overhead. Accumulators hold
//    even/odd-k partials; one horizontal add per dot product.
//  * Input path still folded: gi[j] = dot(K[j][0..7], {1,g,st0..2,g*p0..2}).

#define NB       32768
#define NT       30
#define NH       384
#define ROWS     64
#define NTHREADS 512
#define NGRID    (NB / ROWS)      // 512 CTAs
#define HPAD     388              // float4-aligned, conflict-free LDS.128
#define H64PAD   68               // 16B-aligned row stride for decode hidden
#define UPW      24               // units per warp (384 / 16 warps)
#define GSTRIDE  36864            // 384*384 floats / 4 = gate stride in longlong2

#define SMEM_FLOATS (2*ROWS*HPAD + ROWS*H64PAD + ROWS*3 + ROWS*3 + ROWS)
#define SMEM_BYTES  (SMEM_FLOATS * 4)

// packed f32x2 fma: d += a * b (componentwise), operands are bit-packed pairs
#define FFMA2(d, a, b) \
    asm("fma.rn.f32x2 %0, %1, %2, %0;" : "+l"(d) : "l"(a), "l"(b))

__device__ __forceinline__ float hadd2(unsigned long long v)
{
    float lo = __uint_as_float((unsigned)(v & 0xffffffffULL));
    float hi = __uint_as_float((unsigned)(v >> 32));
    return lo + hi;
}

// Folded input-path coefficients, packed 8 per unit:
// {C2, C1, M2_0, M2_1, M2_2, M1_0, M1_1, M1_2}
__device__ float g_K[1152 * 8];

__global__ void precompute_kernel(const float* __restrict__ Wp,
                                  const float* __restrict__ bp,
                                  const float* __restrict__ Ws,
                                  const float* __restrict__ bs,
                                  const float* __restrict__ Wih,
                                  const float* __restrict__ bih)
{
    int j = blockIdx.x * blockDim.x + threadIdx.x;
    if (j >= 1152) return;
    const float* wr = Wih + j * 128;
    float m10 = 0.f, m11 = 0.f, m12 = 0.f;
    float m20 = 0.f, m21 = 0.f, m22 = 0.f;
    float c1 = 0.f, c2 = 0.f;
#pragma unroll 4
    for (int i = 0; i < 128; ++i) {
        float w = wr[i];
        m10 = fmaf(w, Wp[i * 3 + 0], m10);
        m11 = fmaf(w, Wp[i * 3 + 1], m11);
        m12 = fmaf(w, Wp[i * 3 + 2], m12);
        m20 = fmaf(w, Ws[i * 3 + 0], m20);
        m21 = fmaf(w, Ws[i * 3 + 1], m21);
        m22 = fmaf(w, Ws[i * 3 + 2], m22);
        c1  = fmaf(w, bp[i], c1);
        c2  = fmaf(w, bs[i], c2);
    }
    float* K = g_K + (size_t)j * 8;
    K[0] = c2 + bih[j]; K[1] = c1;
    K[2] = m20; K[3] = m21; K[4] = m22;
    K[5] = m10; K[6] = m11; K[7] = m12;
}

__device__ __forceinline__ float sigf(float x)
{
    return 1.0f / (1.0f + __expf(-x));
}
__device__ __forceinline__ float tanh_f(float x)
{
    return 1.0f - 2.0f / (__expf(2.0f * x) + 1.0f);
}
__device__ __forceinline__ float gi_dot(const float* K,
                                        float g, float s0, float s1, float s2,
                                        float p0, float p1, float p2)
{
    const float4 c0 = *(const float4*)(K);
    const float4 c1 = *(const float4*)(K + 4);
    float a = fmaf(g, c0.y, c0.x);
    a = fmaf(s0, c0.z, a);
    a = fmaf(s1, c0.w, a);
    a = fmaf(s2, c1.x, a);
    a = fmaf(p0, c1.y, a);
    a = fmaf(p1, c1.z, a);
    a = fmaf(p2, c1.w, a);
    return a;
}

__global__ void __launch_bounds__(NTHREADS, 1)
decoder_kernel(const float* __restrict__ init_hidden,
               const float* __restrict__ plan,
               const float* __restrict__ gate,
               const float* __restrict__ init_state,
               const float* __restrict__ Whh,
               const float* __restrict__ bhh,
               const float* __restrict__ Wd1,
               const float* __restrict__ bd1,
               const float* __restrict__ Wd2,
               const float* __restrict__ bd2,
               float* __restrict__ out)
{
    extern __shared__ float smem[];
    float* sh_h     = smem;                       // [2][ROWS][HPAD]
    float* sh_h64   = smem + 2 * ROWS * HPAD;     // [ROWS][H64PAD]
    float* sh_state = sh_h64 + ROWS * H64PAD;     // [ROWS][3]
    float* sh_plan  = sh_state + ROWS * 3;        // [ROWS][3]
    float* sh_gate  = sh_plan + ROWS * 3;         // [ROWS]

    const int tid  = threadIdx.x;
    const int warp = tid >> 5;
    const int lane = tid & 31;
    const int row0 = blockIdx.x * ROWS;
    const int ra   = lane;        // first row owned by this lane
    const int rb   = lane + 32;   // second row

    // ---- init ----
    for (int i = tid; i < ROWS * NH; i += NTHREADS) {
        int r = i / NH, c = i - r * NH;
        sh_h[r * HPAD + c] = init_hidden[(size_t)(row0 + r) * NH + c];
    }
    for (int i = tid; i < ROWS * 3; i += NTHREADS) {
        sh_state[i] = init_state[(size_t)row0 * 3 + i];
        int r = i / 3, c = i - r * 3;
        sh_plan[i] = plan[((size_t)(row0 + r) * NT) * 3 + c];
    }
    if (tid < ROWS) sh_gate[tid] = gate[row0 + tid];
    __syncthreads();

    for (int t = 0; t < NT; ++t) {
        float* hcur = sh_h + (t & 1) * (ROWS * HPAD);
        float* hnxt = sh_h + ((t & 1) ^ 1) * (ROWS * HPAD);

        // per-row folded-gi scalars (both rows)
        const float gA  = sh_gate[ra],            gB  = sh_gate[rb];
        const float sA0 = sh_state[ra * 3 + 0],   sB0 = sh_state[rb * 3 + 0];
        const float sA1 = sh_state[ra * 3 + 1],   sB1 = sh_state[rb * 3 + 1];
        const float sA2 = sh_state[ra * 3 + 2],   sB2 = sh_state[rb * 3 + 2];
        const float pA0 = gA * sh_plan[ra * 3 + 0], pB0 = gB * sh_plan[rb * 3 + 0];
        const float pA1 = gA * sh_plan[ra * 3 + 1], pB1 = gB * sh_plan[rb * 3 + 1];
        const float pA2 = gA * sh_plan[ra * 3 + 2], pB2 = gB * sh_plan[rb * 3 + 2];

        const longlong2* hA = (const longlong2*)(hcur + ra * HPAD);
        const longlong2* hB = (const longlong2*)(hcur + rb * HPAD);

        // ======== Phase 1: GRU GEMV, warp -> units [24w, 24w+24) ========
#pragma unroll 1
        for (int grp = 0; grp < UPW / 4; ++grp) {
            const int jj = warp * UPW + grp * 4;
            // acc[u][gate][row]: f32x2 partial sums over even/odd k
            unsigned long long acc[4][3][2];
#pragma unroll
            for (int u = 0; u < 4; ++u)
#pragma unroll
                for (int gt = 0; gt < 3; ++gt) {
                    acc[u][gt][0] = 0ULL; acc[u][gt][1] = 0ULL;
                }
            const longlong2* wbase = (const longlong2*)(Whh + (size_t)jj * NH);

#pragma unroll 2
            for (int k = 0; k < NH / 4; ++k) {
                const longlong2 ha = hA[k];
                const longlong2 hb = hB[k];
#pragma unroll
                for (int u = 0; u < 4; ++u) {
                    const longlong2* wp = wbase + u * (NH / 4);
                    const longlong2 wr = __ldg(wp + k);
                    const longlong2 wz = __ldg(wp + k + GSTRIDE);
                    const longlong2 wn = __ldg(wp + k + 2 * GSTRIDE);
                    FFMA2(acc[u][0][0], ha.x, wr.x);
                    FFMA2(acc[u][0][0], ha.y, wr.y);
                    FFMA2(acc[u][0][1], hb.x, wr.x);
                    FFMA2(acc[u][0][1], hb.y, wr.y);
                    FFMA2(acc[u][1][0], ha.x, wz.x);
                    FFMA2(acc[u][1][0], ha.y, wz.y);
                    FFMA2(acc[u][1][1], hb.x, wz.x);
                    FFMA2(acc[u][1][1], hb.y, wz.y);
                    FFMA2(acc[u][2][0], ha.x, wn.x);
                    FFMA2(acc[u][2][0], ha.y, wn.y);
                    FFMA2(acc[u][2][1], hb.x, wn.x);
                    FFMA2(acc[u][2][1], hb.y, wn.y);
                }
            }

#pragma unroll
            for (int u = 0; u < 4; ++u) {
                const int j = jj + u;
                const float br_ = __ldg(bhh + j);
                const float bz_ = __ldg(bhh + j + 384);
                const float bn_ = __ldg(bhh + j + 768);
                const float* Kr = g_K + (size_t)j * 8;
                const float* Kz = g_K + (size_t)(j + 384) * 8;
                const float* Kn = g_K + (size_t)(j + 768) * 8;

                // row A
                {
                    float gr = gi_dot(Kr, gA, sA0, sA1, sA2, pA0, pA1, pA2);
                    float gz = gi_dot(Kz, gA, sA0, sA1, sA2, pA0, pA1, pA2);
                    float gn = gi_dot(Kn, gA, sA0, sA1, sA2, pA0, pA1, pA2);
                    float hr = hadd2(acc[u][0][0]) + br_;
                    float hz = hadd2(acc[u][1][0]) + bz_;
                    float hn = hadd2(acc[u][2][0]) + bn_;
                    float r = sigf(gr + hr);
                    float z = sigf(gz + hz);
                    float n = tanh_f(gn + r * hn);
                    float hold = hcur[ra * HPAD + j];
                    hnxt[ra * HPAD + j] = n + z * (hold - n);
                }
                // row B
                {
                    float gr = gi_dot(Kr, gB, sB0, sB1, sB2, pB0, pB1, pB2);
                    float gz = gi_dot(Kz, gB, sB0, sB1, sB2, pB0, pB1, pB2);
                    float gn = gi_dot(Kn, gB, sB0, sB1, sB2, pB0, pB1, pB2);
                    float hr = hadd2(acc[u][0][1]) + br_;
                    float hz = hadd2(acc[u][1][1]) + bz_;
                    float hn = hadd2(acc[u][2][1]) + bn_;
                    float r = sigf(gr + hr);
                    float z = sigf(gz + hz);
                    float n = tanh_f(gn + r * hn);
                    float hold = hcur[rb * HPAD + j];
                    hnxt[rb * HPAD + j] = n + z * (hold - n);
                }
            }
        }
        __syncthreads();

        // ======== Phase 2: decode Linear(384->64) + ELU, 4 units/warp ======
        {
            const int u0 = warp * 4;
            unsigned long long acc[4][2];
#pragma unroll
            for (int u = 0; u < 4; ++u) { acc[u][0] = 0ULL; acc[u][1] = 0ULL; }
            const longlong2* h2A = (const longlong2*)(hnxt + ra * HPAD);
            const longlong2* h2B = (const longlong2*)(hnxt + rb * HPAD);
            const longlong2* wd  = (const longlong2*)(Wd1 + (size_t)u0 * NH);
#pragma unroll 2
            for (int k = 0; k < NH / 4; ++k) {
                const longlong2 ha = h2A[k];
                const longlong2 hb = h2B[k];
#pragma unroll
                for (int u = 0; u < 4; ++u) {
                    const longlong2 w = __ldg(wd + u * (NH / 4) + k);
                    FFMA2(acc[u][0], ha.x, w.x);
                    FFMA2(acc[u][0], ha.y, w.y);
                    FFMA2(acc[u][1], hb.x, w.x);
                    FFMA2(acc[u][1], hb.y, w.y);
                }
            }
#pragma unroll
            for (int u = 0; u < 4; ++u) {
                const float b1 = __ldg(bd1 + u0 + u);
                float va = hadd2(acc[u][0]) + b1;
                float vb = hadd2(acc[u][1]) + b1;
                sh_h64[ra * H64PAD + u0 + u] =
                    (va > 0.0f) ? va : (__expf(va) - 1.0f);
                sh_h64[rb * H64PAD + u0 + u] =
                    (vb > 0.0f) ? vb : (__expf(vb) - 1.0f);
            }
        }
        __syncthreads();

        // ======== Phase 3: decode Linear(64->3), state += dec, emit ========
        if (tid < ROWS * 3) {
            const int brw = tid / 3, v = tid - brw * 3;
            const longlong2* w2 = (const longlong2*)(Wd2 + v * 64);
            const longlong2* hh = (const longlong2*)(sh_h64 + brw * H64PAD);
            unsigned long long a0 = 0ULL, a1 = 0ULL;
#pragma unroll
            for (int k = 0; k < 16; k += 2) {
                const longlong2 wa = __ldg(w2 + k);
                const longlong2 wb = __ldg(w2 + k + 1);
                const longlong2 h0 = hh[k];
                const longlong2 h1 = hh[k + 1];
                FFMA2(a0, h0.x, wa.x);
                FFMA2(a1, h0.y, wa.y);
                FFMA2(a0, h1.x, wb.x);
                FFMA2(a1, h1.y, wb.y);
            }
            float s = sh_state[tid] + hadd2(a0) + hadd2(a1) + __ldg(bd2 + v);
            sh_state[tid] = s;
            out[((size_t)(row0 + brw) * NT + t) * 3 + v] = s;
        } else if (tid >= 256 && tid < 256 + ROWS * 3) {
            if (t + 1 < NT) {   // stage next step's plan in parallel
                const int i  = tid - 256;
                const int brw = i / 3, c = i - brw * 3;
                sh_plan[i] = plan[((size_t)(row0 + brw) * NT + (t + 1)) * 3 + c];
            }
        }
        __syncthreads();
    }
}

extern "C" void kernel_launch(void* const* d_in, const int* in_sizes, int n_in,
                              void* d_out, int out_size)
{
    (void)in_sizes; (void)n_in; (void)out_size;
    const float* init_hidden = (const float*)d_in[0];
    const float* plan        = (const float*)d_in[1];
    const float* gate        = (const float*)d_in[2];
    const float* init_state  = (const float*)d_in[3];
    const float* Wp   = (const float*)d_in[4];
    const float* bp   = (const float*)d_in[5];
    const float* Ws   = (const float*)d_in[6];
    const float* bs   = (const float*)d_in[7];
    const float* W_ih = (const float*)d_in[8];
    const float* b_ih = (const float*)d_in[9];
    const float* W_hh = (const float*)d_in[10];
    const float* b_hh = (const float*)d_in[11];
    const float* Wd1  = (const float*)d_in[12];
    const float* bd1  = (const float*)d_in[13];
    const float* Wd2  = (const float*)d_in[14];
    const float* bd2  = (const float*)d_in[15];
    float* out = (float*)d_out;

    precompute_kernel<<<9, 128>>>(Wp, bp, Ws, bs, W_ih, b_ih);

    cudaFuncSetAttribute(decoder_kernel,
                         cudaFuncAttributeMaxDynamicSharedMemorySize,
                         SMEM_BYTES);
    decoder_kernel<<<NGRID, NTHREADS, SMEM_BYTES>>>(
        init_hidden, plan, gate, init_state,
        W_hh, b_hh, Wd1, bd1, Wd2, bd2, out);
}